// round 1
// baseline (speedup 1.0000x reference)
#include <cuda_runtime.h>
#include <cstdint>

// Problem constants
#define Bn   4
#define Ln   8
#define Nn   2048
#define Cn   32
#define MIDn 64
#define OUTn 128
#define Mn   1024
#define KSn  32
#define KMn  192   // 3*64
#define BLn  32    // B*L

// Scratch (device globals; no allocation allowed)
__device__ float g_ft[BLn * Nn * Cn];          // features transposed: [frame][point][channel]
__device__ float g_x[Bn * Ln * KMn * Mn];      // pre-BN activations x[b,l,km,m]
__device__ float g_mean[Ln * KMn];
__device__ float g_rstd[Ln * KMn];

// ---------------------------------------------------------------------------
// 1) Transpose features (B,L,C,N) -> g_ft[frame][n][c]
// ---------------------------------------------------------------------------
__global__ void transpose_feat_kernel(const float* __restrict__ feat) {
    __shared__ float sm[32][33];
    int f  = blockIdx.y;          // frame 0..31
    int n0 = blockIdx.x * 32;     // point tile
    int tx = threadIdx.x, ty = threadIdx.y;
    // read: feat[f][c=ty][n0+tx]
    sm[ty][tx] = feat[((size_t)f * Cn + ty) * Nn + n0 + tx];
    __syncthreads();
    // write: g_ft[f][n0+ty][c=tx]
    g_ft[((size_t)f * Nn + n0 + ty) * Cn + tx] = sm[tx][ty];
}

// ---------------------------------------------------------------------------
// 2) FPS per frame: 32 blocks, 512 threads, 4 points/thread.
//    Writes anchors (new_xyzs) directly into d_out[0 .. BL*M*3).
// ---------------------------------------------------------------------------
__global__ void fps_kernel(const float* __restrict__ xyz, float* __restrict__ dout) {
    __shared__ float4 pts[Nn];
    __shared__ float  rbv[16];
    __shared__ int    rbi[16];
    __shared__ int    ssel;

    int f   = blockIdx.x;
    int tid = threadIdx.x;
    int lane = tid & 31, wid = tid >> 5;

    const float* base = xyz + (size_t)f * Nn * 3;
    for (int p = tid; p < Nn; p += 512)
        pts[p] = make_float4(base[3*p], base[3*p+1], base[3*p+2], 0.f);
    __syncthreads();

    float px[4], py[4], pz[4], md[4];
#pragma unroll
    for (int j = 0; j < 4; ++j) {
        float4 q = pts[tid + j*512];
        px[j] = q.x; py[j] = q.y; pz[j] = q.z;
        md[j] = 3.4028234663852886e38f;  // FLT_MAX, matches jnp.finfo(f32).max
    }

    int sel = 0;
    for (int i = 0; i < Mn; ++i) {
        float4 sp = pts[sel];
        if (tid == 0) {
            float* o = dout + ((size_t)f * Mn + i) * 3;
            o[0] = sp.x; o[1] = sp.y; o[2] = sp.z;
        }
        float bv = -1.f; int bi = 0x7fffffff;
#pragma unroll
        for (int j = 0; j < 4; ++j) {
            float dx = px[j] - sp.x, dy = py[j] - sp.y, dz = pz[j] - sp.z;
            float d  = dx*dx + dy*dy + dz*dz;
            float nm = fminf(md[j], d);
            md[j] = nm;
            if (nm > bv) { bv = nm; bi = tid + j*512; }  // strict > keeps lowest index
        }
#pragma unroll
        for (int off = 16; off > 0; off >>= 1) {
            float ov = __shfl_down_sync(0xffffffffu, bv, off);
            int   oi = __shfl_down_sync(0xffffffffu, bi, off);
            if (ov > bv || (ov == bv && oi < bi)) { bv = ov; bi = oi; }
        }
        if (lane == 0) { rbv[wid] = bv; rbi[wid] = bi; }
        __syncthreads();
        if (wid == 0) {
            float v  = (lane < 16) ? rbv[lane] : -1.f;
            int   ix = (lane < 16) ? rbi[lane] : 0x7fffffff;
#pragma unroll
            for (int off = 8; off > 0; off >>= 1) {
                float ov = __shfl_down_sync(0xffffffffu, v, off);
                int   oi = __shfl_down_sync(0xffffffffu, ix, off);
                if (ov > v || (ov == v && oi < ix)) { v = ov; ix = oi; }
            }
            if (lane == 0) ssel = ix;
        }
        __syncthreads();
        sel = ssel;
    }
}

// ---------------------------------------------------------------------------
// 3) Ball query + grouped conv via moment matrix S, fused small GEMM.
//    grid: (16 anchor tiles of 64, 3 offsets, 32 frames), 256 threads.
// ---------------------------------------------------------------------------
__global__ void __launch_bounds__(256)
group_conv_kernel(const float* __restrict__ xyz,
                  const float* __restrict__ anchors,   // = d_out xyz section
                  const float* __restrict__ cdw,       // (64,3)
                  const float* __restrict__ cfw)       // (64,32)
{
    extern __shared__ char smraw[];
    float4* npts = (float4*)smraw;                        // 2048 * 16B = 32KB
    float*  Ssm  = (float*)(smraw + 32768);               // 64 * 96 floats
    float*  W2   = (float*)(smraw + 32768 + 24576);       // 64 * 96 floats
    int*    cand = (int*)  (smraw + 32768 + 49152);       // 8 warps * 32

    int tile = blockIdx.x;   // anchor tile (64 anchors)
    int o    = blockIdx.y;   // temporal offset 0..2
    int f    = blockIdx.z;   // frame
    int b = f >> 3, l = f & 7;
    int tid = threadIdx.x, lane = tid & 31, wid = tid >> 5;

    int ln = l + o - 1;      // neighbor frame time
    if (ln < 0 || ln >= Ln) {
        // zero-padded frame contributes exactly 0
        for (int idx = tid; idx < 4096; idx += 256) {
            int kk = idx >> 6, mm = idx & 63;
            g_x[((size_t)f * KMn + o * MIDn + kk) * Mn + tile * 64 + mm] = 0.f;
        }
        return;
    }
    int nbr = b * Ln + ln;

    const float* nb = xyz + (size_t)nbr * Nn * 3;
    for (int p = tid; p < Nn; p += 256)
        npts[p] = make_float4(nb[3*p], nb[3*p+1], nb[3*p+2], 0.f);
    for (int idx = tid; idx < MIDn * 96; idx += 256) {
        int oo = idx / 96, r = idx % 96, c = r / 3, d = r % 3;
        W2[idx] = cfw[oo * Cn + c] * cdw[oo * 3 + d];
    }
    __syncthreads();

    int* candw = cand + wid * 32;
    const float* fb = g_ft + (size_t)nbr * Nn * Cn;

    for (int aa = 0; aa < 8; ++aa) {
        int a_local = wid * 8 + aa;
        int a = tile * 64 + a_local;
        const float* ap = anchors + ((size_t)f * Mn + a) * 3;
        float ax = ap[0], ay = ap[1], az = ap[2];

        // --- ball query: first 32 indices (ascending) with d2 < 0.04 ---
        int cnt = 0;
        for (int basej = 0; basej < Nn && cnt < KSn; basej += 32) {
            int j = basej + lane;
            float4 p = npts[j];
            float dx = p.x - ax, dy = p.y - ay, dz = p.z - az;
            float d2 = dx*dx + dy*dy + dz*dz;
            bool in = d2 < 0.04f;
            unsigned msk = __ballot_sync(0xffffffffu, in);
            if (in) {
                int pos = cnt + __popc(msk & ((1u << lane) - 1u));
                if (pos < KSn) candw[pos] = j;
            }
            cnt += __popc(msk);
        }
        __syncwarp();
        int cc = cnt < KSn ? cnt : KSn;
        int fill0 = (cc > 0) ? candw[0] : 0;
        __syncwarp();
        if (lane >= cc) candw[lane] = fill0;   // never writes slot 0
        __syncwarp();

        // --- moment S[c,d] = sum_k f[k,c] * disp[k,d], lane = channel c ---
        float a0 = 0.f, a1 = 0.f, a2 = 0.f;
#pragma unroll 8
        for (int k = 0; k < KSn; ++k) {
            int j = candw[k];
            float4 p = npts[j];
            float fv = fb[(size_t)j * Cn + lane];   // coalesced 128B per k
            a0 += fv * (p.x - ax);
            a1 += fv * (p.y - ay);
            a2 += fv * (p.z - az);
        }
        Ssm[a_local * 96 + lane * 3 + 0] = a0;
        Ssm[a_local * 96 + lane * 3 + 1] = a1;
        Ssm[a_local * 96 + lane * 3 + 2] = a2;
    }
    __syncthreads();

    // --- GEMM: out[64 o][64 a] = W2[64][96] @ S[96][64] ---
    int o0 = (tid & 15) * 4;
    int aq = (tid >> 4) * 4;
    float acc[4][4] = {};
    for (int i = 0; i < 96; i += 4) {
        float4 w[4], s[4];
#pragma unroll
        for (int q = 0; q < 4; ++q) w[q] = *(const float4*)&W2[(o0 + q) * 96 + i];
#pragma unroll
        for (int q = 0; q < 4; ++q) s[q] = *(const float4*)&Ssm[(aq + q) * 96 + i];
#pragma unroll
        for (int q = 0; q < 4; ++q)
#pragma unroll
            for (int r = 0; r < 4; ++r)
                acc[q][r] += w[q].x * s[r].x + w[q].y * s[r].y
                           + w[q].z * s[r].z + w[q].w * s[r].w;
    }
#pragma unroll
    for (int q = 0; q < 4; ++q)
#pragma unroll
        for (int r = 0; r < 4; ++r)
            g_x[((size_t)f * KMn + o * MIDn + o0 + q) * Mn + tile * 64 + aq + r] = acc[q][r];
}

// ---------------------------------------------------------------------------
// 4) BN stats per (l, km) over (B, M) = 4096 values
// ---------------------------------------------------------------------------
__global__ void stats_kernel() {
    int pair = blockIdx.x;               // l*192 + km
    int l = pair / KMn, km = pair % KMn;
    int tid = threadIdx.x;
    float s1 = 0.f, s2 = 0.f;
    for (int b = 0; b < Bn; ++b) {
        const float* row = g_x + ((size_t)((b * Ln + l) * KMn + km)) * Mn;
        for (int m = tid; m < Mn; m += 128) {
            float v = row[m];
            s1 += v; s2 += v * v;
        }
    }
    __shared__ float sh1[4], sh2[4];
#pragma unroll
    for (int off = 16; off > 0; off >>= 1) {
        s1 += __shfl_down_sync(0xffffffffu, s1, off);
        s2 += __shfl_down_sync(0xffffffffu, s2, off);
    }
    int lane = tid & 31, w = tid >> 5;
    if (lane == 0) { sh1[w] = s1; sh2[w] = s2; }
    __syncthreads();
    if (tid == 0) {
        float t1 = sh1[0] + sh1[1] + sh1[2] + sh1[3];
        float t2 = sh2[0] + sh2[1] + sh2[2] + sh2[3];
        float mean = t1 * (1.f / 4096.f);
        float var  = t2 * (1.f / 4096.f) - mean * mean;
        g_mean[pair] = mean;
        g_rstd[pair] = rsqrtf(var + 1e-5f);
    }
}

// ---------------------------------------------------------------------------
// 5) Fused BN + ReLU + temporal GEMM: out[f][128][m] = TW @ relu(bn(x))
//    grid: (8 m-tiles, 32 frames), 256 threads, 192KB smem.
// ---------------------------------------------------------------------------
__global__ void __launch_bounds__(256)
bn_gemm_kernel(const float* __restrict__ gamma, const float* __restrict__ beta,
               const float* __restrict__ tw, float* __restrict__ dout)
{
    extern __shared__ float smf[];
    float* xsm  = smf;           // [192][128]
    float* twsm = smf + 24576;   // [128][192]

    int f = blockIdx.y, l = f & 7;
    int mb = blockIdx.x * 128;
    int tid = threadIdx.x;

    for (int idx = tid; idx < KMn * 128; idx += 256) {
        int k = idx >> 7, m = idx & 127;
        float v  = g_x[((size_t)f * KMn + k) * Mn + mb + m];
        float xn = (v - g_mean[l * KMn + k]) * g_rstd[l * KMn + k] * gamma[k] + beta[k];
        xsm[idx] = fmaxf(xn, 0.f);
    }
    for (int idx = tid; idx < OUTn * KMn; idx += 256) twsm[idx] = tw[idx];
    __syncthreads();

    int o0 = (tid >> 4) * 8;
    int m0 = (tid & 15) * 8;
    float acc[8][8] = {};
    for (int k = 0; k < KMn; k += 4) {
        float4 wv[8];
#pragma unroll
        for (int q = 0; q < 8; ++q) wv[q] = *(const float4*)&twsm[(o0 + q) * KMn + k];
        float4 xa[4], xb[4];
#pragma unroll
        for (int j = 0; j < 4; ++j) {
            xa[j] = *(const float4*)&xsm[(k + j) * 128 + m0];
            xb[j] = *(const float4*)&xsm[(k + j) * 128 + m0 + 4];
        }
#pragma unroll
        for (int q = 0; q < 8; ++q) {
            const float* wq = (const float*)&wv[q];
#pragma unroll
            for (int j = 0; j < 4; ++j) {
                float w = wq[j];
                const float* pa = (const float*)&xa[j];
                const float* pb = (const float*)&xb[j];
#pragma unroll
                for (int r = 0; r < 4; ++r) {
                    acc[q][r]     += w * pa[r];
                    acc[q][4 + r] += w * pb[r];
                }
            }
        }
    }
    float* outb = dout + (size_t)BLn * Mn * 3 + ((size_t)f * OUTn) * Mn + mb;
#pragma unroll
    for (int q = 0; q < 8; ++q)
#pragma unroll
        for (int r = 0; r < 8; ++r)
            outb[(size_t)(o0 + q) * Mn + m0 + r] = acc[q][r];
}

// ---------------------------------------------------------------------------
extern "C" void kernel_launch(void* const* d_in, const int* in_sizes, int n_in,
                              void* d_out, int out_size) {
    const float* xyzs     = (const float*)d_in[0];
    const float* features = (const float*)d_in[1];
    const float* cdw      = (const float*)d_in[2];
    const float* cfw      = (const float*)d_in[3];
    const float* gamma    = (const float*)d_in[4];
    const float* beta     = (const float*)d_in[5];
    const float* tw       = (const float*)d_in[6];
    float* out = (float*)d_out;

    cudaFuncSetAttribute(group_conv_kernel, cudaFuncAttributeMaxDynamicSharedMemorySize, 82944);
    cudaFuncSetAttribute(bn_gemm_kernel,    cudaFuncAttributeMaxDynamicSharedMemorySize, 196608);

    transpose_feat_kernel<<<dim3(64, 32), dim3(32, 32)>>>(features);
    fps_kernel<<<32, 512>>>(xyzs, out);
    group_conv_kernel<<<dim3(16, 3, 32), 256, 82944>>>(xyzs, out, cdw, cfw);
    stats_kernel<<<Ln * KMn, 128>>>();
    bn_gemm_kernel<<<dim3(8, 32), 256, 196608>>>(gamma, beta, tw, out);
}